// round 2
// baseline (speedup 1.0000x reference)
#include <cuda_runtime.h>
#include <math.h>

#define T_LEN 512
#define BSZ   256
#define DIM   512
#define HID   512
#define M_TOT (T_LEN * BSZ)   /* 131072 */
#define N4    (4 * HID)       /* 2048   */

// Scratch: input projections [T][B][4H] (f,i,o,a blocks of H each), 1 GiB.
__device__ float g_Y[268435456];          // 131072 * 2048
// Cell state [B][H]
__device__ float g_c[BSZ * HID];

// ---------------------------------------------------------------------------
// GEMM1: Y[t*B+b][g*H+n] = sum_k X[t*B+b][k] * W_g[n][k]  (+ bias for g<3)
// M=131072, N=2048, K=512. Tiles: BM=128, BN=64, BK=16, 128 threads, 8x8/thread.
// ---------------------------------------------------------------------------
__global__ __launch_bounds__(128) void gemm_xproj(
    const float* __restrict__ X,
    const float* __restrict__ Wf, const float* __restrict__ Wi,
    const float* __restrict__ Wo, const float* __restrict__ Wa,
    const float* __restrict__ bf, const float* __restrict__ bi,
    const float* __restrict__ bo)
{
    const int BM = 128, BN = 64, BK = 16;
    __shared__ __align__(16) float As[BK][BM];
    __shared__ __align__(16) float Bs[BK][BN];

    const int nTile = blockIdx.x;          // 0..31
    const int mBase = blockIdx.y * BM;     // 0..1023 tiles
    const int gate  = nTile >> 3;          // 8 n-tiles per gate (512/64)
    const int nInG  = (nTile & 7) * BN;    // col offset within the gate

    const float* W    = (gate == 0) ? Wf : (gate == 1) ? Wi : (gate == 2) ? Wo : Wa;
    const float* bias = (gate == 0) ? bf : (gate == 1) ? bi : (gate == 2) ? bo : nullptr;

    const int tid = threadIdx.x;
    const int ty  = tid >> 3;   // 0..15 -> row group (8 rows)
    const int tx  = tid & 7;    // 0..7  -> col group (8 cols)

    float acc[8][8];
#pragma unroll
    for (int i = 0; i < 8; i++)
#pragma unroll
        for (int j = 0; j < 8; j++) acc[i][j] = 0.f;

    for (int kb = 0; kb < DIM; kb += BK) {
        // Load A tile: 128 rows x 16 k = 512 float4; 4 per thread.
#pragma unroll
        for (int l = 0; l < 4; l++) {
            int idx = tid + l * 128;
            int row = idx >> 2;         // 0..127
            int kv  = idx & 3;          // float4 index within the 16-k row
            float4 v = *reinterpret_cast<const float4*>(
                X + (size_t)(mBase + row) * DIM + kb + kv * 4);
            As[kv * 4 + 0][row] = v.x;
            As[kv * 4 + 1][row] = v.y;
            As[kv * 4 + 2][row] = v.z;
            As[kv * 4 + 3][row] = v.w;
        }
        // Load B tile: 64 rows(n) x 16 k = 256 float4; 2 per thread.
#pragma unroll
        for (int l = 0; l < 2; l++) {
            int idx = tid + l * 128;
            int row = idx >> 2;         // n within tile, 0..63
            int kv  = idx & 3;
            float4 v = *reinterpret_cast<const float4*>(
                W + (size_t)(nInG + row) * DIM + kb + kv * 4);
            Bs[kv * 4 + 0][row] = v.x;
            Bs[kv * 4 + 1][row] = v.y;
            Bs[kv * 4 + 2][row] = v.z;
            Bs[kv * 4 + 3][row] = v.w;
        }
        __syncthreads();

#pragma unroll
        for (int k = 0; k < BK; k++) {
            float4 a0 = *reinterpret_cast<const float4*>(&As[k][ty * 8]);
            float4 a1 = *reinterpret_cast<const float4*>(&As[k][ty * 8 + 4]);
            float4 b0 = *reinterpret_cast<const float4*>(&Bs[k][tx * 8]);
            float4 b1 = *reinterpret_cast<const float4*>(&Bs[k][tx * 8 + 4]);
            float a[8] = {a0.x, a0.y, a0.z, a0.w, a1.x, a1.y, a1.z, a1.w};
            float b[8] = {b0.x, b0.y, b0.z, b0.w, b1.x, b1.y, b1.z, b1.w};
#pragma unroll
            for (int i = 0; i < 8; i++)
#pragma unroll
                for (int j = 0; j < 8; j++)
                    acc[i][j] = fmaf(a[i], b[j], acc[i][j]);
        }
        __syncthreads();
    }

    // Epilogue: add bias (gate<3), store float4 pairs.
    const int nBase = nTile * BN;
    float bv[8];
#pragma unroll
    for (int j = 0; j < 8; j++)
        bv[j] = bias ? bias[nInG + tx * 8 + j] : 0.f;

#pragma unroll
    for (int i = 0; i < 8; i++) {
        size_t row = (size_t)(mBase + ty * 8 + i);
        float* yrow = g_Y + row * N4 + nBase + tx * 8;
        float4 o0, o1;
        o0.x = acc[i][0] + bv[0]; o0.y = acc[i][1] + bv[1];
        o0.z = acc[i][2] + bv[2]; o0.w = acc[i][3] + bv[3];
        o1.x = acc[i][4] + bv[4]; o1.y = acc[i][5] + bv[5];
        o1.z = acc[i][6] + bv[6]; o1.w = acc[i][7] + bv[7];
        *reinterpret_cast<float4*>(yrow)     = o0;
        *reinterpret_cast<float4*>(yrow + 4) = o1;
    }
}

// ---------------------------------------------------------------------------
// One recurrence step: a = h_prev @ W_aa^T + b_a, then fused gates.
// M=256(B), N=512(H), K=512. Tiles: BM=32, BN=32, BK=32, 128 threads, 2x4/thread.
// Grid: (16, 8) = 128 blocks.
// ---------------------------------------------------------------------------
__device__ __forceinline__ float sigf(float x) {
    return 1.f / (1.f + __expf(-x));
}
__device__ __forceinline__ float tanh_fast(float x) {
    return 2.f / (1.f + __expf(-2.f * x)) - 1.f;
}

__global__ __launch_bounds__(128) void lstm_step(
    const float* __restrict__ Waa,
    const float* __restrict__ ba,
    const float* __restrict__ h_prev,   // nullptr for t == 0
    float*       __restrict__ out,      // d_out base, [T][B][H]
    float*       __restrict__ hn,       // nullptr unless t == T-1
    int t)
{
    const int BM = 32, BN = 32, BK = 32;
    __shared__ __align__(16) float As[BK][BM];
    __shared__ __align__(16) float Bs[BK][BN];

    const int tid = threadIdx.x;
    const int ty = tid >> 3;          // 0..15 -> m group (2 rows)
    const int tx = tid & 7;           // 0..7  -> n group (4 cols)
    const int mBase = blockIdx.y * BM;   // B dim
    const int nBase = blockIdx.x * BN;   // H dim

    float acc[2][4];
#pragma unroll
    for (int i = 0; i < 2; i++)
#pragma unroll
        for (int j = 0; j < 4; j++) acc[i][j] = 0.f;

    if (h_prev) {
        for (int kb = 0; kb < HID; kb += BK) {
            // A tile: 32 rows x 32 k = 256 float4; 2 per thread.
#pragma unroll
            for (int l = 0; l < 2; l++) {
                int idx = tid + l * 128;
                int row = idx >> 3;      // 0..31
                int kv  = idx & 7;       // 8 float4 per 32-k row
                float4 v = *reinterpret_cast<const float4*>(
                    h_prev + (size_t)(mBase + row) * HID + kb + kv * 4);
                As[kv * 4 + 0][row] = v.x;
                As[kv * 4 + 1][row] = v.y;
                As[kv * 4 + 2][row] = v.z;
                As[kv * 4 + 3][row] = v.w;
            }
            // B tile: Waa[n][k], 32 rows x 32 k.
#pragma unroll
            for (int l = 0; l < 2; l++) {
                int idx = tid + l * 128;
                int row = idx >> 3;
                int kv  = idx & 7;
                float4 v = *reinterpret_cast<const float4*>(
                    Waa + (size_t)(nBase + row) * HID + kb + kv * 4);
                Bs[kv * 4 + 0][row] = v.x;
                Bs[kv * 4 + 1][row] = v.y;
                Bs[kv * 4 + 2][row] = v.z;
                Bs[kv * 4 + 3][row] = v.w;
            }
            __syncthreads();

#pragma unroll
            for (int k = 0; k < BK; k++) {
                float a0 = As[k][ty * 2 + 0];
                float a1 = As[k][ty * 2 + 1];
                float4 b = *reinterpret_cast<const float4*>(&Bs[k][tx * 4]);
                acc[0][0] = fmaf(a0, b.x, acc[0][0]);
                acc[0][1] = fmaf(a0, b.y, acc[0][1]);
                acc[0][2] = fmaf(a0, b.z, acc[0][2]);
                acc[0][3] = fmaf(a0, b.w, acc[0][3]);
                acc[1][0] = fmaf(a1, b.x, acc[1][0]);
                acc[1][1] = fmaf(a1, b.y, acc[1][1]);
                acc[1][2] = fmaf(a1, b.z, acc[1][2]);
                acc[1][3] = fmaf(a1, b.w, acc[1][3]);
            }
            __syncthreads();
        }
    }

    // Fused gate epilogue.
    const float* Yt = g_Y + (size_t)t * BSZ * N4;
    const int n0 = nBase + tx * 4;
    const float4 ba4 = *reinterpret_cast<const float4*>(ba + n0);

#pragma unroll
    for (int i = 0; i < 2; i++) {
        const int m = mBase + ty * 2 + i;
        const float* yr = Yt + (size_t)m * N4;
        float4 xf = *reinterpret_cast<const float4*>(yr + n0);
        float4 xi = *reinterpret_cast<const float4*>(yr + HID + n0);
        float4 xo = *reinterpret_cast<const float4*>(yr + 2 * HID + n0);
        float4 xa = *reinterpret_cast<const float4*>(yr + 3 * HID + n0);
        float4 c4 = make_float4(0.f, 0.f, 0.f, 0.f);
        if (h_prev)
            c4 = *reinterpret_cast<const float4*>(g_c + (size_t)m * HID + n0);

        float av[4] = {acc[i][0] + ba4.x, acc[i][1] + ba4.y,
                       acc[i][2] + ba4.z, acc[i][3] + ba4.w};
        float xfv[4] = {xf.x, xf.y, xf.z, xf.w};
        float xiv[4] = {xi.x, xi.y, xi.z, xi.w};
        float xov[4] = {xo.x, xo.y, xo.z, xo.w};
        float xav[4] = {xa.x, xa.y, xa.z, xa.w};
        float cv[4]  = {c4.x, c4.y, c4.z, c4.w};

        float cn[4], hv[4];
#pragma unroll
        for (int j = 0; j < 4; j++) {
            float a  = av[j];
            float ft = sigf(xfv[j] + a);
            float it = sigf(xiv[j] + a);
            float ot = sigf(xov[j] + a);
            float g  = tanh_fast(xav[j] + a);
            cn[j] = ft * cv[j] + it * g;
            hv[j] = ot * tanh_fast(cn[j]);
        }
        float4 cno = make_float4(cn[0], cn[1], cn[2], cn[3]);
        float4 ho  = make_float4(hv[0], hv[1], hv[2], hv[3]);
        *reinterpret_cast<float4*>(g_c + (size_t)m * HID + n0) = cno;
        *reinterpret_cast<float4*>(out + ((size_t)t * BSZ + m) * HID + n0) = ho;
        if (hn)
            *reinterpret_cast<float4*>(hn + (size_t)m * HID + n0) = ho;
    }
}

// ---------------------------------------------------------------------------
extern "C" void kernel_launch(void* const* d_in, const int* in_sizes, int n_in,
                              void* d_out, int out_size)
{
    (void)in_sizes; (void)n_in;
    const float* X   = (const float*)d_in[0];
    const float* Wf  = (const float*)d_in[1];
    const float* Wi  = (const float*)d_in[2];
    const float* Wo  = (const float*)d_in[3];
    const float* Wa  = (const float*)d_in[4];
    const float* Waa = (const float*)d_in[5];
    const float* bf  = (const float*)d_in[6];
    const float* bi  = (const float*)d_in[7];
    const float* bo  = (const float*)d_in[8];
    const float* ba  = (const float*)d_in[9];
    float* out = (float*)d_out;

    // Input projections: Y = X @ [Wf;Wi;Wo;Wa]^T (+bias for f,i,o)
    dim3 g1(32, 1024);
    gemm_xproj<<<g1, 128>>>(X, Wf, Wi, Wo, Wa, bf, bi, bo);

    const size_t step_elems = (size_t)BSZ * HID;            // 131072
    const size_t outs_elems = (size_t)T_LEN * step_elems;   // 67108864
    float* hn_ptr = ((size_t)out_size >= outs_elems + step_elems)
                        ? out + outs_elems : nullptr;

    dim3 gs(16, 8);  // H tiles x B tiles = 128 blocks
    for (int t = 0; t < T_LEN; t++) {
        const float* hprev = (t == 0) ? nullptr
                                      : out + (size_t)(t - 1) * step_elems;
        float* hn = (t == T_LEN - 1) ? hn_ptr : nullptr;
        lstm_step<<<gs, 128>>>(Waa, ba, hprev, out, hn, t);
    }
}

// round 3
// speedup vs baseline: 1.2145x; 1.2145x over previous
#include <cuda_runtime.h>
#include <math.h>

#define T_LEN 512
#define BSZ   256
#define DIM   512
#define HID   512
#define N4    (4 * HID)       /* 2048 */

// Scratch: input projections [T][B][4H] (f,i,o,a blocks of H each).
__device__ float g_Y[268435456];          // 131072 * 2048

// Grid barrier state (separate 128B lines to avoid L2 line contention).
__device__ unsigned g_sync[64];           // g_sync[0] = count, g_sync[32] = gen

// ---------------------------------------------------------------------------
// GEMM1: Y[t*B+b][g*H+n] = sum_k X[t*B+b][k] * W_g[n][k]  (+ bias for g<3)
// M=131072, N=2048, K=512. Tiles: BM=128, BN=64, BK=16, 128 threads, 8x8/thread.
// ---------------------------------------------------------------------------
__global__ __launch_bounds__(128) void gemm_xproj(
    const float* __restrict__ X,
    const float* __restrict__ Wf, const float* __restrict__ Wi,
    const float* __restrict__ Wo, const float* __restrict__ Wa,
    const float* __restrict__ bf, const float* __restrict__ bi,
    const float* __restrict__ bo)
{
    const int BM = 128, BN = 64, BK = 16;
    __shared__ __align__(16) float As[BK][BM];
    __shared__ __align__(16) float Bs[BK][BN];

    const int nTile = blockIdx.x;          // 0..31
    const int mBase = blockIdx.y * BM;
    const int gate  = nTile >> 3;
    const int nInG  = (nTile & 7) * BN;

    const float* W    = (gate == 0) ? Wf : (gate == 1) ? Wi : (gate == 2) ? Wo : Wa;
    const float* bias = (gate == 0) ? bf : (gate == 1) ? bi : (gate == 2) ? bo : nullptr;

    const int tid = threadIdx.x;
    const int ty  = tid >> 3;
    const int tx  = tid & 7;

    float acc[8][8];
#pragma unroll
    for (int i = 0; i < 8; i++)
#pragma unroll
        for (int j = 0; j < 8; j++) acc[i][j] = 0.f;

    for (int kb = 0; kb < DIM; kb += BK) {
#pragma unroll
        for (int l = 0; l < 4; l++) {
            int idx = tid + l * 128;
            int row = idx >> 2;
            int kv  = idx & 3;
            float4 v = *reinterpret_cast<const float4*>(
                X + (size_t)(mBase + row) * DIM + kb + kv * 4);
            As[kv * 4 + 0][row] = v.x;
            As[kv * 4 + 1][row] = v.y;
            As[kv * 4 + 2][row] = v.z;
            As[kv * 4 + 3][row] = v.w;
        }
#pragma unroll
        for (int l = 0; l < 2; l++) {
            int idx = tid + l * 128;
            int row = idx >> 2;
            int kv  = idx & 3;
            float4 v = *reinterpret_cast<const float4*>(
                W + (size_t)(nInG + row) * DIM + kb + kv * 4);
            Bs[kv * 4 + 0][row] = v.x;
            Bs[kv * 4 + 1][row] = v.y;
            Bs[kv * 4 + 2][row] = v.z;
            Bs[kv * 4 + 3][row] = v.w;
        }
        __syncthreads();

#pragma unroll
        for (int k = 0; k < BK; k++) {
            float4 a0 = *reinterpret_cast<const float4*>(&As[k][ty * 8]);
            float4 a1 = *reinterpret_cast<const float4*>(&As[k][ty * 8 + 4]);
            float4 b0 = *reinterpret_cast<const float4*>(&Bs[k][tx * 8]);
            float4 b1 = *reinterpret_cast<const float4*>(&Bs[k][tx * 8 + 4]);
            float a[8] = {a0.x, a0.y, a0.z, a0.w, a1.x, a1.y, a1.z, a1.w};
            float b[8] = {b0.x, b0.y, b0.z, b0.w, b1.x, b1.y, b1.z, b1.w};
#pragma unroll
            for (int i = 0; i < 8; i++)
#pragma unroll
                for (int j = 0; j < 8; j++)
                    acc[i][j] = fmaf(a[i], b[j], acc[i][j]);
        }
        __syncthreads();
    }

    const int nBase = nTile * BN;
    float bv[8];
#pragma unroll
    for (int j = 0; j < 8; j++)
        bv[j] = bias ? bias[nInG + tx * 8 + j] : 0.f;

#pragma unroll
    for (int i = 0; i < 8; i++) {
        size_t row = (size_t)(mBase + ty * 8 + i);
        float* yrow = g_Y + row * N4 + nBase + tx * 8;
        float4 o0, o1;
        o0.x = acc[i][0] + bv[0]; o0.y = acc[i][1] + bv[1];
        o0.z = acc[i][2] + bv[2]; o0.w = acc[i][3] + bv[3];
        o1.x = acc[i][4] + bv[4]; o1.y = acc[i][5] + bv[5];
        o1.z = acc[i][6] + bv[6]; o1.w = acc[i][7] + bv[7];
        *reinterpret_cast<float4*>(yrow)     = o0;
        *reinterpret_cast<float4*>(yrow + 4) = o1;
    }
}

// ---------------------------------------------------------------------------
// Persistent recurrence kernel. 128 blocks (16 n-tiles x 8 m-tiles), 128 thr.
// Block tile: 32 B-rows x 32 H-cols. Thread: 1 m-row (lane) x 8 n-cols (warp).
// W_aa slice resident in smem (k-major). c in registers. Grid barrier / step.
// ---------------------------------------------------------------------------
__device__ __forceinline__ float sigf(float x) {
    return 1.f / (1.f + __expf(-x));
}
__device__ __forceinline__ float tanh_fast(float x) {
    return 2.f / (1.f + __expf(-2.f * x)) - 1.f;
}

__global__ __launch_bounds__(128, 1) void lstm_persistent(
    const float* __restrict__ Waa,
    const float* __restrict__ ba,
    float*       __restrict__ out,     // [T][B][H]
    float*       __restrict__ hn)      // may be null
{
    extern __shared__ float sm[];
    float* Ws = sm;            // [512][32] k-major: Ws[k*32 + n_local]
    float* hs = sm + 16384;    // [512][32] k-major, col = m ^ ((k>>2)&31)

    const int tid  = threadIdx.x;
    const int lane = tid & 31;
    const int w    = tid >> 5;           // warp 0..3
    const int nBase = (blockIdx.x & 15) * 32;
    const int mBase = (blockIdx.x >> 4) * 32;
    const int n0 = w * 8;                // warp's n offset within tile
    const int m  = lane;                 // thread's m row within tile
    const unsigned nblk = gridDim.x;

    // One-time: load Waa[nBase+nl][k] -> Ws[k][nl].
    for (int e = tid; e < 4096; e += 128) {
        int nl = e & 31;                 // lanes -> distinct smem banks
        int k4 = e >> 5;                 // 0..127
        float4 v = *reinterpret_cast<const float4*>(
            Waa + (size_t)(nBase + nl) * HID + k4 * 4);
        Ws[(k4 * 4 + 0) * 32 + nl] = v.x;
        Ws[(k4 * 4 + 1) * 32 + nl] = v.y;
        Ws[(k4 * 4 + 2) * 32 + nl] = v.z;
        Ws[(k4 * 4 + 3) * 32 + nl] = v.w;
    }

    float ban[8];
#pragma unroll
    for (int j = 0; j < 8; j++) ban[j] = ba[nBase + n0 + j];

    float c[8];
#pragma unroll
    for (int j = 0; j < 8; j++) c[j] = 0.f;

    __syncthreads();

    volatile unsigned* genp = &g_sync[32];

    for (int t = 0; t < T_LEN; t++) {
        float acc[8];
#pragma unroll
        for (int j = 0; j < 8; j++) acc[j] = 0.f;

        if (t > 0) {
            // Stage h(t-1) tile: global [m][k] -> hs[k][m ^ ((k>>2)&31)].
            const float* hsrc = out + ((size_t)(t - 1) * BSZ + mBase) * HID;
#pragma unroll
            for (int i = 0; i < 32; i++) {
                int e  = tid + i * 128;      // 0..4095
                int mm = e >> 7;             // 0..31
                int k4 = e & 127;            // lanes consecutive -> coalesced
                float4 v = *reinterpret_cast<const float4*>(
                    hsrc + (size_t)mm * HID + k4 * 4);
                int col = mm ^ (k4 & 31);    // conflict-free stores & reads
                hs[(k4 * 4 + 0) * 32 + col] = v.x;
                hs[(k4 * 4 + 1) * 32 + col] = v.y;
                hs[(k4 * 4 + 2) * 32 + col] = v.z;
                hs[(k4 * 4 + 3) * 32 + col] = v.w;
            }
            __syncthreads();

            // a[m][n0..n0+7] += sum_k h[m][k] * Waa[n][k]
#pragma unroll 4
            for (int kq = 0; kq < 128; kq++) {
                const int col = m ^ (kq & 31);
                const float* hp = hs + kq * 128 + col;
                const float* wp = Ws + kq * 128 + n0;
#pragma unroll
                for (int j = 0; j < 4; j++) {
                    float a = hp[j * 32];
                    float4 b0 = *reinterpret_cast<const float4*>(wp + j * 32);
                    float4 b1 = *reinterpret_cast<const float4*>(wp + j * 32 + 4);
                    acc[0] = fmaf(a, b0.x, acc[0]);
                    acc[1] = fmaf(a, b0.y, acc[1]);
                    acc[2] = fmaf(a, b0.z, acc[2]);
                    acc[3] = fmaf(a, b0.w, acc[3]);
                    acc[4] = fmaf(a, b1.x, acc[4]);
                    acc[5] = fmaf(a, b1.y, acc[5]);
                    acc[6] = fmaf(a, b1.z, acc[6]);
                    acc[7] = fmaf(a, b1.w, acc[7]);
                }
            }
        }

        // Fused gate epilogue (c stays in registers).
        const float* yr = g_Y + ((size_t)t * BSZ + mBase + m) * N4 + nBase + n0;
        float* hout = out + ((size_t)t * BSZ + mBase + m) * HID + nBase + n0;
#pragma unroll
        for (int q = 0; q < 2; q++) {
            float4 xf = *reinterpret_cast<const float4*>(yr + q * 4);
            float4 xi = *reinterpret_cast<const float4*>(yr + HID + q * 4);
            float4 xo = *reinterpret_cast<const float4*>(yr + 2 * HID + q * 4);
            float4 xa = *reinterpret_cast<const float4*>(yr + 3 * HID + q * 4);
            float xfv[4] = {xf.x, xf.y, xf.z, xf.w};
            float xiv[4] = {xi.x, xi.y, xi.z, xi.w};
            float xov[4] = {xo.x, xo.y, xo.z, xo.w};
            float xav[4] = {xa.x, xa.y, xa.z, xa.w};
            float hv[4];
#pragma unroll
            for (int j = 0; j < 4; j++) {
                int o = q * 4 + j;
                float a  = acc[o] + ban[o];
                float ft = sigf(xfv[j] + a);
                float it = sigf(xiv[j] + a);
                float ot = sigf(xov[j] + a);
                float g  = tanh_fast(xav[j] + a);
                c[o] = ft * c[o] + it * g;
                hv[j] = ot * tanh_fast(c[o]);
            }
            float4 ho = make_float4(hv[0], hv[1], hv[2], hv[3]);
            *reinterpret_cast<float4*>(hout + q * 4) = ho;
            if (hn && t == T_LEN - 1)
                *reinterpret_cast<float4*>(
                    hn + (size_t)(mBase + m) * HID + nBase + n0 + q * 4) = ho;
        }

        // Grid barrier (not needed after the final step).
        if (t < T_LEN - 1) {
            __syncthreads();
            if (tid == 0) {
                unsigned gen = *genp;            // snapshot BEFORE arriving
                __threadfence();                 // publish h(t) writes
                if (atomicAdd(&g_sync[0], 1u) == nblk - 1) {
                    atomicExch(&g_sync[0], 0u);  // reset count for next barrier
                    __threadfence();
                    *genp = gen + 1;             // release
                } else {
                    while (*genp == gen) { }
                }
                __threadfence();                 // acquire
            }
            __syncthreads();
        }
    }
}

// ---------------------------------------------------------------------------
extern "C" void kernel_launch(void* const* d_in, const int* in_sizes, int n_in,
                              void* d_out, int out_size)
{
    (void)in_sizes; (void)n_in;
    const float* X   = (const float*)d_in[0];
    const float* Wf  = (const float*)d_in[1];
    const float* Wi  = (const float*)d_in[2];
    const float* Wo  = (const float*)d_in[3];
    const float* Wa  = (const float*)d_in[4];
    const float* Waa = (const float*)d_in[5];
    const float* bf  = (const float*)d_in[6];
    const float* bi  = (const float*)d_in[7];
    const float* bo  = (const float*)d_in[8];
    const float* ba  = (const float*)d_in[9];
    float* out = (float*)d_out;

    // Input projections: Y = X @ [Wf;Wi;Wo;Wa]^T (+bias for f,i,o)
    dim3 g1(32, 1024);
    gemm_xproj<<<g1, 128>>>(X, Wf, Wi, Wo, Wa, bf, bi, bo);

    const size_t step_elems = (size_t)BSZ * HID;            // 131072
    const size_t outs_elems = (size_t)T_LEN * step_elems;   // 67108864
    float* hn_ptr = ((size_t)out_size >= outs_elems + step_elems)
                        ? out + outs_elems : nullptr;

    const int smem_bytes = 2 * 512 * 32 * (int)sizeof(float);   // 128 KB
    static bool attr_set = false;
    if (!attr_set) {
        cudaFuncSetAttribute(lstm_persistent,
                             cudaFuncAttributeMaxDynamicSharedMemorySize,
                             smem_bytes);
        attr_set = true;
    }
    lstm_persistent<<<128, 128, smem_bytes>>>(Waa, ba, out, hn_ptr);
}

// round 5
// speedup vs baseline: 1.7793x; 1.4650x over previous
#include <cuda_runtime.h>
#include <cuda_bf16.h>
#include <math.h>
#include <cstdint>

#define T_LEN 512
#define BSZ   256
#define DIM   512
#define HID   512
#define N4    (4 * HID)       /* 2048 */

// Scratch: input projections [T][B][4H] (f,i,o,a blocks of H each).
__device__ float g_Y[268435456];          // 131072 * 2048
// Grid barrier state.
__device__ unsigned g_sync[64];

// ============================================================================
// helpers
// ============================================================================
__device__ __forceinline__ uint32_t smem_u32(const void* p) {
    uint32_t a;
    asm("{ .reg .u64 t; cvta.to.shared.u64 t, %1; cvt.u32.u64 %0, t; }"
        : "=r"(a) : "l"(p));
    return a;
}

__device__ __forceinline__ void ldsm_x4(uint32_t& r0, uint32_t& r1,
                                        uint32_t& r2, uint32_t& r3,
                                        uint32_t addr) {
    asm volatile("ldmatrix.sync.aligned.m8n8.x4.shared.b16 {%0,%1,%2,%3}, [%4];"
                 : "=r"(r0), "=r"(r1), "=r"(r2), "=r"(r3) : "r"(addr));
}

__device__ __forceinline__ void mma16816(float* c, const uint32_t* a,
                                         uint32_t b0, uint32_t b1) {
    asm volatile(
        "mma.sync.aligned.m16n8k16.row.col.f32.bf16.bf16.f32 "
        "{%0,%1,%2,%3}, {%4,%5,%6,%7}, {%8,%9}, {%0,%1,%2,%3};"
        : "+f"(c[0]), "+f"(c[1]), "+f"(c[2]), "+f"(c[3])
        : "r"(a[0]), "r"(a[1]), "r"(a[2]), "r"(a[3]), "r"(b0), "r"(b1));
}

// fp32 -> bf16 hi/lo split, packed pairwise (first elem in low half).
__device__ __forceinline__ void split2(float x, float y, uint32_t& hi, uint32_t& lo) {
    __nv_bfloat16 hx = __float2bfloat16(x);
    __nv_bfloat16 hy = __float2bfloat16(y);
    float rx = x - __bfloat162float(hx);
    float ry = y - __bfloat162float(hy);
    __nv_bfloat16 lx = __float2bfloat16(rx);
    __nv_bfloat16 ly = __float2bfloat16(ry);
    __nv_bfloat162 hp = __nv_bfloat162(hx, hy);
    __nv_bfloat162 lp = __nv_bfloat162(lx, ly);
    hi = *reinterpret_cast<uint32_t*>(&hp);
    lo = *reinterpret_cast<uint32_t*>(&lp);
}

// ============================================================================
// Tensor-core GEMM1 via mma.sync bf16 hi/lo split:
//   Y = X @ [Wf;Wi;Wo;Wa]^T (+bias for f,i,o), fp32 acc.
// CTA 128x128, K chunk 64, 256 thr (8 warps = 4m x 2n, warp tile 32x64).
// smem tiles (bf16, 16B-chunk XOR swizzle): AH|AL|BH|BL at 16KB each.
// ============================================================================
__global__ __launch_bounds__(256, 2) void gemm_xproj_mma(
    const float* __restrict__ X,
    const float* __restrict__ Wf, const float* __restrict__ Wi,
    const float* __restrict__ Wo, const float* __restrict__ Wa,
    const float* __restrict__ bf, const float* __restrict__ bi,
    const float* __restrict__ bo)
{
    extern __shared__ __align__(128) char smem[];
    const uint32_t sb = smem_u32(smem);
    const uint32_t AH = 0, AL = 16384, BH = 32768, BL = 49152;

    const int tid  = threadIdx.x;
    const int lane = tid & 31;
    const int wid  = tid >> 5;
    const int wm   = wid >> 1;   // 0..3
    const int wn   = wid & 1;    // 0..1

    const int nTile = blockIdx.x;            // 0..15 (128 cols each)
    const int mBase = blockIdx.y * 128;
    const int gate  = nTile >> 2;
    const int rowG  = (nTile & 3) * 128;

    const float* W    = (gate == 0) ? Wf : (gate == 1) ? Wi : (gate == 2) ? Wo : Wa;
    const float* bias = (gate == 0) ? bf : (gate == 1) ? bi : (gate == 2) ? bo : nullptr;

    float c[2][8][4];
#pragma unroll
    for (int mf = 0; mf < 2; mf++)
#pragma unroll
        for (int nf = 0; nf < 8; nf++)
#pragma unroll
            for (int q = 0; q < 4; q++) c[mf][nf][q] = 0.f;

    // per-thread staging indices (row, col-group of 8 floats)
    const int srow = tid >> 3;          // 0..31 (+32*it)
    const int cg   = (tid & 7) * 8;     // 0..56

    for (int chunk = 0; chunk < 8; chunk++) {
        const int kb = chunk * 64;
        const float* Asrc = X + (size_t)mBase * DIM + kb;
        const float* Bsrc = W + (size_t)rowG  * DIM + kb;

#pragma unroll
        for (int it = 0; it < 4; it++) {
            const int row = srow + it * 32;
            const uint32_t off =
                (uint32_t)row * 128 + ((((cg >> 3) ^ (row & 7))) << 4);
            {
                float4 v0 = *reinterpret_cast<const float4*>(
                    Asrc + (size_t)row * DIM + cg);
                float4 v1 = *reinterpret_cast<const float4*>(
                    Asrc + (size_t)row * DIM + cg + 4);
                uint32_t h0, h1, h2, h3, l0, l1, l2, l3;
                split2(v0.x, v0.y, h0, l0);
                split2(v0.z, v0.w, h1, l1);
                split2(v1.x, v1.y, h2, l2);
                split2(v1.z, v1.w, h3, l3);
                *reinterpret_cast<uint4*>(smem + AH + off) = make_uint4(h0, h1, h2, h3);
                *reinterpret_cast<uint4*>(smem + AL + off) = make_uint4(l0, l1, l2, l3);
            }
            {
                float4 v0 = *reinterpret_cast<const float4*>(
                    Bsrc + (size_t)row * DIM + cg);
                float4 v1 = *reinterpret_cast<const float4*>(
                    Bsrc + (size_t)row * DIM + cg + 4);
                uint32_t h0, h1, h2, h3, l0, l1, l2, l3;
                split2(v0.x, v0.y, h0, l0);
                split2(v0.z, v0.w, h1, l1);
                split2(v1.x, v1.y, h2, l2);
                split2(v1.z, v1.w, h3, l3);
                *reinterpret_cast<uint4*>(smem + BH + off) = make_uint4(h0, h1, h2, h3);
                *reinterpret_cast<uint4*>(smem + BL + off) = make_uint4(l0, l1, l2, l3);
            }
        }
        __syncthreads();

#pragma unroll
        for (int ks = 0; ks < 4; ks++) {
            const int chv = ks * 2 + (lane >> 4);

            uint32_t ah[2][4], al[2][4];
#pragma unroll
            for (int mf = 0; mf < 2; mf++) {
                const int row = wm * 32 + mf * 16 + (lane & 15);
                const uint32_t addr =
                    sb + (uint32_t)row * 128 + (((chv ^ (row & 7))) << 4);
                ldsm_x4(ah[mf][0], ah[mf][1], ah[mf][2], ah[mf][3], addr + AH);
                ldsm_x4(al[mf][0], al[mf][1], al[mf][2], al[mf][3], addr + AL);
            }

            {
                uint32_t bh[4][4];
#pragma unroll
                for (int np = 0; np < 4; np++) {
                    const int row = wn * 64 + np * 16 + (lane & 15);
                    const uint32_t addr =
                        sb + BH + (uint32_t)row * 128 + (((chv ^ (row & 7))) << 4);
                    ldsm_x4(bh[np][0], bh[np][1], bh[np][2], bh[np][3], addr);
                }
#pragma unroll
                for (int mf = 0; mf < 2; mf++)
#pragma unroll
                    for (int nf = 0; nf < 8; nf++) {
                        const int np = nf >> 1, s = nf & 1;
                        mma16816(c[mf][nf], ah[mf], bh[np][s], bh[np][s + 2]);
                        mma16816(c[mf][nf], al[mf], bh[np][s], bh[np][s + 2]);
                    }
            }
            {
                uint32_t bl[4][4];
#pragma unroll
                for (int np = 0; np < 4; np++) {
                    const int row = wn * 64 + np * 16 + (lane & 15);
                    const uint32_t addr =
                        sb + BL + (uint32_t)row * 128 + (((chv ^ (row & 7))) << 4);
                    ldsm_x4(bl[np][0], bl[np][1], bl[np][2], bl[np][3], addr);
                }
#pragma unroll
                for (int mf = 0; mf < 2; mf++)
#pragma unroll
                    for (int nf = 0; nf < 8; nf++) {
                        const int np = nf >> 1, s = nf & 1;
                        mma16816(c[mf][nf], ah[mf], bl[np][s], bl[np][s + 2]);
                    }
            }
        }
        __syncthreads();
    }

    // Epilogue: add bias, write fp32 to g_Y.
    const int colBase = nTile * 128 + wn * 64 + (lane & 3) * 2;
    const int rBase   = mBase + wm * 32 + (lane >> 2);
#pragma unroll
    for (int nf = 0; nf < 8; nf++) {
        const int col = colBase + nf * 8;
        const int ln  = wn * 64 + nf * 8 + (lane & 3) * 2;   // 0..127 in tile
        float b0 = bias ? __ldg(bias + rowG + ln)     : 0.f;
        float b1 = bias ? __ldg(bias + rowG + ln + 1) : 0.f;
#pragma unroll
        for (int mf = 0; mf < 2; mf++) {
            const size_t r0 = (size_t)(rBase + mf * 16);
            float2 o0 = make_float2(c[mf][nf][0] + b0, c[mf][nf][1] + b1);
            float2 o1 = make_float2(c[mf][nf][2] + b0, c[mf][nf][3] + b1);
            *reinterpret_cast<float2*>(g_Y + r0 * N4 + col)       = o0;
            *reinterpret_cast<float2*>(g_Y + (r0 + 8) * N4 + col) = o1;
        }
    }
}

// ---------------------------------------------------------------------------
// Persistent recurrence kernel (unchanged from round 3).
// ---------------------------------------------------------------------------
__device__ __forceinline__ float sigf(float x) {
    return 1.f / (1.f + __expf(-x));
}
__device__ __forceinline__ float tanh_fast(float x) {
    return 2.f / (1.f + __expf(-2.f * x)) - 1.f;
}

__global__ __launch_bounds__(128, 1) void lstm_persistent(
    const float* __restrict__ Waa,
    const float* __restrict__ ba,
    float*       __restrict__ out,
    float*       __restrict__ hn)
{
    extern __shared__ float sm[];
    float* Ws = sm;
    float* hs = sm + 16384;

    const int tid  = threadIdx.x;
    const int lane = tid & 31;
    const int w    = tid >> 5;
    const int nBase = (blockIdx.x & 15) * 32;
    const int mBase = (blockIdx.x >> 4) * 32;
    const int n0 = w * 8;
    const int m  = lane;
    const unsigned nblk = gridDim.x;

    for (int e = tid; e < 4096; e += 128) {
        int nl = e & 31;
        int k4 = e >> 5;
        float4 v = *reinterpret_cast<const float4*>(
            Waa + (size_t)(nBase + nl) * HID + k4 * 4);
        Ws[(k4 * 4 + 0) * 32 + nl] = v.x;
        Ws[(k4 * 4 + 1) * 32 + nl] = v.y;
        Ws[(k4 * 4 + 2) * 32 + nl] = v.z;
        Ws[(k4 * 4 + 3) * 32 + nl] = v.w;
    }

    float ban[8];
#pragma unroll
    for (int j = 0; j < 8; j++) ban[j] = ba[nBase + n0 + j];

    float c[8];
#pragma unroll
    for (int j = 0; j < 8; j++) c[j] = 0.f;

    __syncthreads();

    volatile unsigned* genp = &g_sync[32];

    for (int t = 0; t < T_LEN; t++) {
        float acc[8];
#pragma unroll
        for (int j = 0; j < 8; j++) acc[j] = 0.f;

        if (t > 0) {
            const float* hsrc = out + ((size_t)(t - 1) * BSZ + mBase) * HID;
#pragma unroll
            for (int i = 0; i < 32; i++) {
                int e  = tid + i * 128;
                int mm = e >> 7;
                int k4 = e & 127;
                float4 v = *reinterpret_cast<const float4*>(
                    hsrc + (size_t)mm * HID + k4 * 4);
                int col = mm ^ (k4 & 31);
                hs[(k4 * 4 + 0) * 32 + col] = v.x;
                hs[(k4 * 4 + 1) * 32 + col] = v.y;
                hs[(k4 * 4 + 2) * 32 + col] = v.z;
                hs[(k4 * 4 + 3) * 32 + col] = v.w;
            }
            __syncthreads();

#pragma unroll 4
            for (int kq = 0; kq < 128; kq++) {
                const int col = m ^ (kq & 31);
                const float* hp = hs + kq * 128 + col;
                const float* wp = Ws + kq * 128 + n0;
#pragma unroll
                for (int j = 0; j < 4; j++) {
                    float a = hp[j * 32];
                    float4 b0 = *reinterpret_cast<const float4*>(wp + j * 32);
                    float4 b1 = *reinterpret_cast<const float4*>(wp + j * 32 + 4);
                    acc[0] = fmaf(a, b0.x, acc[0]);
                    acc[1] = fmaf(a, b0.y, acc[1]);
                    acc[2] = fmaf(a, b0.z, acc[2]);
                    acc[3] = fmaf(a, b0.w, acc[3]);
                    acc[4] = fmaf(a, b1.x, acc[4]);
                    acc[5] = fmaf(a, b1.y, acc[5]);
                    acc[6] = fmaf(a, b1.z, acc[6]);
                    acc[7] = fmaf(a, b1.w, acc[7]);
                }
            }
        }

        const float* yr = g_Y + ((size_t)t * BSZ + mBase + m) * N4 + nBase + n0;
        float* hout = out + ((size_t)t * BSZ + mBase + m) * HID + nBase + n0;
#pragma unroll
        for (int q = 0; q < 2; q++) {
            float4 xf = *reinterpret_cast<const float4*>(yr + q * 4);
            float4 xi = *reinterpret_cast<const float4*>(yr + HID + q * 4);
            float4 xo = *reinterpret_cast<const float4*>(yr + 2 * HID + q * 4);
            float4 xa = *reinterpret_cast<const float4*>(yr + 3 * HID + q * 4);
            float xfv[4] = {xf.x, xf.y, xf.z, xf.w};
            float xiv[4] = {xi.x, xi.y, xi.z, xi.w};
            float xov[4] = {xo.x, xo.y, xo.z, xo.w};
            float xav[4] = {xa.x, xa.y, xa.z, xa.w};
            float hv[4];
#pragma unroll
            for (int j = 0; j < 4; j++) {
                int o = q * 4 + j;
                float a  = acc[o] + ban[o];
                float ft = sigf(xfv[j] + a);
                float it = sigf(xiv[j] + a);
                float ot = sigf(xov[j] + a);
                float g  = tanh_fast(xav[j] + a);
                c[o] = ft * c[o] + it * g;
                hv[j] = ot * tanh_fast(c[o]);
            }
            float4 ho = make_float4(hv[0], hv[1], hv[2], hv[3]);
            *reinterpret_cast<float4*>(hout + q * 4) = ho;
            if (hn && t == T_LEN - 1)
                *reinterpret_cast<float4*>(
                    hn + (size_t)(mBase + m) * HID + nBase + n0 + q * 4) = ho;
        }

        if (t < T_LEN - 1) {
            __syncthreads();
            if (tid == 0) {
                unsigned gen = *genp;
                __threadfence();
                if (atomicAdd(&g_sync[0], 1u) == nblk - 1) {
                    atomicExch(&g_sync[0], 0u);
                    __threadfence();
                    *genp = gen + 1;
                } else {
                    while (*genp == gen) { }
                }
                __threadfence();
            }
            __syncthreads();
        }
    }
}

// ---------------------------------------------------------------------------
extern "C" void kernel_launch(void* const* d_in, const int* in_sizes, int n_in,
                              void* d_out, int out_size)
{
    (void)in_sizes; (void)n_in;
    const float* X   = (const float*)d_in[0];
    const float* Wf  = (const float*)d_in[1];
    const float* Wi  = (const float*)d_in[2];
    const float* Wo  = (const float*)d_in[3];
    const float* Wa  = (const float*)d_in[4];
    const float* Waa = (const float*)d_in[5];
    const float* bf  = (const float*)d_in[6];
    const float* bi  = (const float*)d_in[7];
    const float* bo  = (const float*)d_in[8];
    const float* ba  = (const float*)d_in[9];
    float* out = (float*)d_out;

    const int gemm_smem = 65536;                              // 64 KB
    const int rec_smem  = 2 * 512 * 32 * (int)sizeof(float);  // 128 KB
    static bool attr_set = false;
    if (!attr_set) {
        cudaFuncSetAttribute(gemm_xproj_mma,
                             cudaFuncAttributeMaxDynamicSharedMemorySize,
                             gemm_smem);
        cudaFuncSetAttribute(lstm_persistent,
                             cudaFuncAttributeMaxDynamicSharedMemorySize,
                             rec_smem);
        attr_set = true;
    }

    dim3 g1(16, 1024);
    gemm_xproj_mma<<<g1, 256, gemm_smem>>>(X, Wf, Wi, Wo, Wa, bf, bi, bo);

    const size_t step_elems = (size_t)BSZ * HID;
    const size_t outs_elems = (size_t)T_LEN * step_elems;
    float* hn_ptr = ((size_t)out_size >= outs_elems + step_elems)
                        ? out + outs_elems : nullptr;

    lstm_persistent<<<128, 128, rec_smem>>>(Waa, ba, out, hn_ptr);
}

// round 6
// speedup vs baseline: 1.8012x; 1.0123x over previous
#include <cuda_runtime.h>
#include <cuda_bf16.h>
#include <math.h>
#include <cstdint>

#define T_LEN 512
#define BSZ   256
#define DIM   512
#define HID   512
#define N4    (4 * HID)       /* 2048 */

// Scratch: input projections [T][B][4H].
__device__ float g_Y[268435456];               // 131072 * 2048
// bf16 hi/lo copies of X and W (W rows: gate*512 + r, gates f,i,o,a).
__device__ __nv_bfloat16 g_Xh[67108864];       // 131072 * 512
__device__ __nv_bfloat16 g_Xl[67108864];
__device__ __nv_bfloat16 g_Wh[1048576];        // 2048 * 512
__device__ __nv_bfloat16 g_Wl[1048576];
// Grid barrier state.
__device__ unsigned g_sync[64];

// ============================================================================
// helpers
// ============================================================================
__device__ __forceinline__ uint32_t smem_u32(const void* p) {
    uint32_t a;
    asm("{ .reg .u64 t; cvta.to.shared.u64 t, %1; cvt.u32.u64 %0, t; }"
        : "=r"(a) : "l"(p));
    return a;
}
__device__ __forceinline__ void ldsm_x4(uint32_t& r0, uint32_t& r1,
                                        uint32_t& r2, uint32_t& r3,
                                        uint32_t addr) {
    asm volatile("ldmatrix.sync.aligned.m8n8.x4.shared.b16 {%0,%1,%2,%3}, [%4];"
                 : "=r"(r0), "=r"(r1), "=r"(r2), "=r"(r3) : "r"(addr));
}
__device__ __forceinline__ void mma16816(float* c, const uint32_t* a,
                                         uint32_t b0, uint32_t b1) {
    asm volatile(
        "mma.sync.aligned.m16n8k16.row.col.f32.bf16.bf16.f32 "
        "{%0,%1,%2,%3}, {%4,%5,%6,%7}, {%8,%9}, {%0,%1,%2,%3};"
        : "+f"(c[0]), "+f"(c[1]), "+f"(c[2]), "+f"(c[3])
        : "r"(a[0]), "r"(a[1]), "r"(a[2]), "r"(a[3]), "r"(b0), "r"(b1));
}
#define CP_ASYNC16(dst, src) \
    asm volatile("cp.async.cg.shared.global [%0], [%1], 16;" \
                 :: "r"(dst), "l"(src) : "memory")
#define CP_COMMIT() asm volatile("cp.async.commit_group;" ::: "memory")
#define CP_WAIT(n)  asm volatile("cp.async.wait_group %0;" :: "n"(n) : "memory")

// fp32 -> bf16 hi/lo split, packed pairwise.
__device__ __forceinline__ void split2(float x, float y, uint32_t& hi, uint32_t& lo) {
    __nv_bfloat16 hx = __float2bfloat16(x);
    __nv_bfloat16 hy = __float2bfloat16(y);
    float rx = x - __bfloat162float(hx);
    float ry = y - __bfloat162float(hy);
    __nv_bfloat16 lx = __float2bfloat16(rx);
    __nv_bfloat16 ly = __float2bfloat16(ry);
    __nv_bfloat162 hp = __nv_bfloat162(hx, hy);
    __nv_bfloat162 lp = __nv_bfloat162(lx, ly);
    hi = *reinterpret_cast<uint32_t*>(&hp);
    lo = *reinterpret_cast<uint32_t*>(&lp);
}

// ============================================================================
// One-time conversion kernels.
// ============================================================================
__global__ __launch_bounds__(256) void convert_x(const float* __restrict__ X) {
    size_t i = (size_t)blockIdx.x * blockDim.x + threadIdx.x;   // per float4
    float4 v = reinterpret_cast<const float4*>(X)[i];
    uint32_t h0, h1, l0, l1;
    split2(v.x, v.y, h0, l0);
    split2(v.z, v.w, h1, l1);
    reinterpret_cast<uint2*>(g_Xh)[i] = make_uint2(h0, h1);
    reinterpret_cast<uint2*>(g_Xl)[i] = make_uint2(l0, l1);
}
__global__ __launch_bounds__(256) void convert_w(
    const float* __restrict__ Wf, const float* __restrict__ Wi,
    const float* __restrict__ Wo, const float* __restrict__ Wa) {
    size_t i = (size_t)blockIdx.x * blockDim.x + threadIdx.x;   // per float4
    int gate = (int)(i >> 16);                  // 65536 float4 per gate
    const float* W = (gate == 0) ? Wf : (gate == 1) ? Wi : (gate == 2) ? Wo : Wa;
    float4 v = reinterpret_cast<const float4*>(W)[i & 65535];
    uint32_t h0, h1, l0, l1;
    split2(v.x, v.y, h0, l0);
    split2(v.z, v.w, h1, l1);
    reinterpret_cast<uint2*>(g_Wh)[i] = make_uint2(h0, h1);
    reinterpret_cast<uint2*>(g_Wl)[i] = make_uint2(l0, l1);
}

// ============================================================================
// Tensor-core GEMM1 (bf16 hi/lo 3-term, fp32 acc), cp.async 2-stage pipeline.
// CTA 128x128, K chunk 64, 256 thr (8 warps = 4m x 2n, warp tile 32x64).
// Stage layout (64KB): AH|AL|BH|BL @ 16KB, XOR-swizzled 16B chunks.
// ============================================================================
__global__ __launch_bounds__(256, 1) void gemm_xproj_mma(
    const float* __restrict__ bf, const float* __restrict__ bi,
    const float* __restrict__ bo)
{
    extern __shared__ __align__(128) char smem[];
    const uint32_t sb = smem_u32(smem);

    const int tid  = threadIdx.x;
    const int lane = tid & 31;
    const int wid  = tid >> 5;
    const int wm   = wid >> 1;   // 0..3
    const int wn   = wid & 1;    // 0..1

    const int nTile = blockIdx.x;            // 0..15
    const int mBase = blockIdx.y * 128;
    const int gate  = nTile >> 2;
    const int rowG  = (nTile & 3) * 128;
    const float* bias = (gate == 0) ? bf : (gate == 1) ? bi : (gate == 2) ? bo : nullptr;

    const __nv_bfloat16* Ah = g_Xh + (size_t)mBase * DIM;
    const __nv_bfloat16* Al = g_Xl + (size_t)mBase * DIM;
    const __nv_bfloat16* Bh = g_Wh + (size_t)nTile * 128 * DIM;
    const __nv_bfloat16* Bl = g_Wl + (size_t)nTile * 128 * DIM;

    float c[2][8][4];
#pragma unroll
    for (int mf = 0; mf < 2; mf++)
#pragma unroll
        for (int nf = 0; nf < 8; nf++)
#pragma unroll
            for (int q = 0; q < 4; q++) c[mf][nf][q] = 0.f;

    // --- staging: chunk -> stage buffer s (16 cp.async of 16B per thread) ---
    auto stage = [&](int chunk, int s) {
        const int kb = chunk * 64;
        const uint32_t sOff = (uint32_t)s * 65536;
#pragma unroll
        for (int it = 0; it < 4; it++) {
            int idx = tid + it * 256;
            int row = idx >> 3;           // 0..127
            int ch  = idx & 7;            // 16B chunk in row
            uint32_t off = sOff + (uint32_t)row * 128 + ((ch ^ (row & 7)) << 4);
            const size_t g = (size_t)row * DIM + kb + ch * 8;
            CP_ASYNC16(sb + off,         Ah + g);
            CP_ASYNC16(sb + off + 16384, Al + g);
            CP_ASYNC16(sb + off + 32768, Bh + g);
            CP_ASYNC16(sb + off + 49152, Bl + g);
        }
        CP_COMMIT();
    };

    stage(0, 0);

    for (int chunk = 0; chunk < 8; chunk++) {
        if (chunk < 7) {
            stage(chunk + 1, (chunk + 1) & 1);
            CP_WAIT(1);
        } else {
            CP_WAIT(0);
        }
        __syncthreads();

        const uint32_t sOff = (uint32_t)(chunk & 1) * 65536;
        const uint32_t AH = sOff, AL = sOff + 16384, BH = sOff + 32768, BL = sOff + 49152;

#pragma unroll
        for (int ks = 0; ks < 4; ks++) {
            const int chv = ks * 2 + (lane >> 4);

            uint32_t ah[2][4], al[2][4];
#pragma unroll
            for (int mf = 0; mf < 2; mf++) {
                const int row = wm * 32 + mf * 16 + (lane & 15);
                const uint32_t addr =
                    sb + (uint32_t)row * 128 + (((chv ^ (row & 7))) << 4);
                ldsm_x4(ah[mf][0], ah[mf][1], ah[mf][2], ah[mf][3], addr + AH);
                ldsm_x4(al[mf][0], al[mf][1], al[mf][2], al[mf][3], addr + AL);
            }
            {
                uint32_t bh[4][4];
#pragma unroll
                for (int np = 0; np < 4; np++) {
                    const int row = wn * 64 + np * 16 + (lane & 15);
                    const uint32_t addr =
                        sb + BH + (uint32_t)row * 128 + (((chv ^ (row & 7))) << 4);
                    ldsm_x4(bh[np][0], bh[np][1], bh[np][2], bh[np][3], addr);
                }
#pragma unroll
                for (int mf = 0; mf < 2; mf++)
#pragma unroll
                    for (int nf = 0; nf < 8; nf++) {
                        const int np = nf >> 1, s = nf & 1;
                        mma16816(c[mf][nf], ah[mf], bh[np][s], bh[np][s + 2]);
                        mma16816(c[mf][nf], al[mf], bh[np][s], bh[np][s + 2]);
                    }
            }
            {
                uint32_t bl[4][4];
#pragma unroll
                for (int np = 0; np < 4; np++) {
                    const int row = wn * 64 + np * 16 + (lane & 15);
                    const uint32_t addr =
                        sb + BL + (uint32_t)row * 128 + (((chv ^ (row & 7))) << 4);
                    ldsm_x4(bl[np][0], bl[np][1], bl[np][2], bl[np][3], addr);
                }
#pragma unroll
                for (int mf = 0; mf < 2; mf++)
#pragma unroll
                    for (int nf = 0; nf < 8; nf++) {
                        const int np = nf >> 1, s = nf & 1;
                        mma16816(c[mf][nf], ah[mf], bl[np][s], bl[np][s + 2]);
                    }
            }
        }
        __syncthreads();
    }

    // Epilogue: add bias, write fp32 to g_Y.
    const int colBase = nTile * 128 + wn * 64 + (lane & 3) * 2;
    const int rBase   = mBase + wm * 32 + (lane >> 2);
#pragma unroll
    for (int nf = 0; nf < 8; nf++) {
        const int col = colBase + nf * 8;
        const int ln  = wn * 64 + nf * 8 + (lane & 3) * 2;
        float b0 = bias ? __ldg(bias + rowG + ln)     : 0.f;
        float b1 = bias ? __ldg(bias + rowG + ln + 1) : 0.f;
#pragma unroll
        for (int mf = 0; mf < 2; mf++) {
            const size_t r0 = (size_t)(rBase + mf * 16);
            float2 o0 = make_float2(c[mf][nf][0] + b0, c[mf][nf][1] + b1);
            float2 o1 = make_float2(c[mf][nf][2] + b0, c[mf][nf][3] + b1);
            *reinterpret_cast<float2*>(g_Y + r0 * N4 + col)       = o0;
            *reinterpret_cast<float2*>(g_Y + (r0 + 8) * N4 + col) = o1;
        }
    }
}

// ---------------------------------------------------------------------------
// Persistent recurrence kernel (unchanged).
// ---------------------------------------------------------------------------
__device__ __forceinline__ float sigf(float x) {
    return 1.f / (1.f + __expf(-x));
}
__device__ __forceinline__ float tanh_fast(float x) {
    return 2.f / (1.f + __expf(-2.f * x)) - 1.f;
}

__global__ __launch_bounds__(128, 1) void lstm_persistent(
    const float* __restrict__ Waa,
    const float* __restrict__ ba,
    float*       __restrict__ out,
    float*       __restrict__ hn)
{
    extern __shared__ float sm[];
    float* Ws = sm;
    float* hs = sm + 16384;

    const int tid  = threadIdx.x;
    const int lane = tid & 31;
    const int w    = tid >> 5;
    const int nBase = (blockIdx.x & 15) * 32;
    const int mBase = (blockIdx.x >> 4) * 32;
    const int n0 = w * 8;
    const int m  = lane;
    const unsigned nblk = gridDim.x;

    for (int e = tid; e < 4096; e += 128) {
        int nl = e & 31;
        int k4 = e >> 5;
        float4 v = *reinterpret_cast<const float4*>(
            Waa + (size_t)(nBase + nl) * HID + k4 * 4);
        Ws[(k4 * 4 + 0) * 32 + nl] = v.x;
        Ws[(k4 * 4 + 1) * 32 + nl] = v.y;
        Ws[(k4 * 4 + 2) * 32 + nl] = v.z;
        Ws[(k4 * 4 + 3) * 32 + nl] = v.w;
    }

    float ban[8];
#pragma unroll
    for (int j = 0; j < 8; j++) ban[j] = ba[nBase + n0 + j];

    float c[8];
#pragma unroll
    for (int j = 0; j < 8; j++) c[j] = 0.f;

    __syncthreads();

    volatile unsigned* genp = &g_sync[32];

    for (int t = 0; t < T_LEN; t++) {
        float acc[8];
#pragma unroll
        for (int j = 0; j < 8; j++) acc[j] = 0.f;

        if (t > 0) {
            const float* hsrc = out + ((size_t)(t - 1) * BSZ + mBase) * HID;
#pragma unroll
            for (int i = 0; i < 32; i++) {
                int e  = tid + i * 128;
                int mm = e >> 7;
                int k4 = e & 127;
                float4 v = *reinterpret_cast<const float4*>(
                    hsrc + (size_t)mm * HID + k4 * 4);
                int col = mm ^ (k4 & 31);
                hs[(k4 * 4 + 0) * 32 + col] = v.x;
                hs[(k4 * 4 + 1) * 32 + col] = v.y;
                hs[(k4 * 4 + 2) * 32 + col] = v.z;
                hs[(k4 * 4 + 3) * 32 + col] = v.w;
            }
            __syncthreads();

#pragma unroll 4
            for (int kq = 0; kq < 128; kq++) {
                const int col = m ^ (kq & 31);
                const float* hp = hs + kq * 128 + col;
                const float* wp = Ws + kq * 128 + n0;
#pragma unroll
                for (int j = 0; j < 4; j++) {
                    float a = hp[j * 32];
                    float4 b0 = *reinterpret_cast<const float4*>(wp + j * 32);
                    float4 b1 = *reinterpret_cast<const float4*>(wp + j * 32 + 4);
                    acc[0] = fmaf(a, b0.x, acc[0]);
                    acc[1] = fmaf(a, b0.y, acc[1]);
                    acc[2] = fmaf(a, b0.z, acc[2]);
                    acc[3] = fmaf(a, b0.w, acc[3]);
                    acc[4] = fmaf(a, b1.x, acc[4]);
                    acc[5] = fmaf(a, b1.y, acc[5]);
                    acc[6] = fmaf(a, b1.z, acc[6]);
                    acc[7] = fmaf(a, b1.w, acc[7]);
                }
            }
        }

        const float* yr = g_Y + ((size_t)t * BSZ + mBase + m) * N4 + nBase + n0;
        float* hout = out + ((size_t)t * BSZ + mBase + m) * HID + nBase + n0;
#pragma unroll
        for (int q = 0; q < 2; q++) {
            float4 xf = *reinterpret_cast<const float4*>(yr + q * 4);
            float4 xi = *reinterpret_cast<const float4*>(yr + HID + q * 4);
            float4 xo = *reinterpret_cast<const float4*>(yr + 2 * HID + q * 4);
            float4 xa = *reinterpret_cast<const float4*>(yr + 3 * HID + q * 4);
            float xfv[4] = {xf.x, xf.y, xf.z, xf.w};
            float xiv[4] = {xi.x, xi.y, xi.z, xi.w};
            float xov[4] = {xo.x, xo.y, xo.z, xo.w};
            float xav[4] = {xa.x, xa.y, xa.z, xa.w};
            float hv[4];
#pragma unroll
            for (int j = 0; j < 4; j++) {
                int o = q * 4 + j;
                float a  = acc[o] + ban[o];
                float ft = sigf(xfv[j] + a);
                float it = sigf(xiv[j] + a);
                float ot = sigf(xov[j] + a);
                float g  = tanh_fast(xav[j] + a);
                c[o] = ft * c[o] + it * g;
                hv[j] = ot * tanh_fast(c[o]);
            }
            float4 ho = make_float4(hv[0], hv[1], hv[2], hv[3]);
            *reinterpret_cast<float4*>(hout + q * 4) = ho;
            if (hn && t == T_LEN - 1)
                *reinterpret_cast<float4*>(
                    hn + (size_t)(mBase + m) * HID + nBase + n0 + q * 4) = ho;
        }

        if (t < T_LEN - 1) {
            __syncthreads();
            if (tid == 0) {
                unsigned gen = *genp;
                __threadfence();
                if (atomicAdd(&g_sync[0], 1u) == nblk - 1) {
                    atomicExch(&g_sync[0], 0u);
                    __threadfence();
                    *genp = gen + 1;
                } else {
                    while (*genp == gen) { }
                }
                __threadfence();
            }
            __syncthreads();
        }
    }
}

// ---------------------------------------------------------------------------
extern "C" void kernel_launch(void* const* d_in, const int* in_sizes, int n_in,
                              void* d_out, int out_size)
{
    (void)in_sizes; (void)n_in;
    const float* X   = (const float*)d_in[0];
    const float* Wf  = (const float*)d_in[1];
    const float* Wi  = (const float*)d_in[2];
    const float* Wo  = (const float*)d_in[3];
    const float* Wa  = (const float*)d_in[4];
    const float* Waa = (const float*)d_in[5];
    const float* bf  = (const float*)d_in[6];
    const float* bi  = (const float*)d_in[7];
    const float* bo  = (const float*)d_in[8];
    const float* ba  = (const float*)d_in[9];
    float* out = (float*)d_out;

    const int gemm_smem = 131072;                             // 128 KB
    const int rec_smem  = 2 * 512 * 32 * (int)sizeof(float);  // 128 KB
    static bool attr_set = false;
    if (!attr_set) {
        cudaFuncSetAttribute(gemm_xproj_mma,
                             cudaFuncAttributeMaxDynamicSharedMemorySize,
                             gemm_smem);
        cudaFuncSetAttribute(lstm_persistent,
                             cudaFuncAttributeMaxDynamicSharedMemorySize,
                             rec_smem);
        attr_set = true;
    }

    // One-time bf16 hi/lo conversion.
    convert_x<<<65536, 256>>>(X);                 // 131072*512/4 float4
    convert_w<<<1024, 256>>>(Wf, Wi, Wo, Wa);     // 2048*512/4 float4

    dim3 g1(16, 1024);
    gemm_xproj_mma<<<g1, 256, gemm_smem>>>(bf, bi, bo);

    const size_t step_elems = (size_t)BSZ * HID;
    const size_t outs_elems = (size_t)T_LEN * step_elems;
    float* hn_ptr = ((size_t)out_size >= outs_elems + step_elems)
                        ? out + outs_elems : nullptr;

    lstm_persistent<<<128, 128, rec_smem>>>(Waa, ba, out, hn_ptr);
}